// round 5
// baseline (speedup 1.0000x reference)
#include <cuda_runtime.h>
#include <cuda_fp16.h>

// bg: (1, 4, 32, 32, 32, 16) f32   -> d_in[0]
// gm: (1, 1, 128, 128, 128) f32    -> d_in[1]
// out:(1, 4, 128, 128, 128) f32

#define GH 128
#define GWD 128
#define GD 128
#define H 32
#define W 32
#define D 32
#define UP 16
#define TH 4
#define TW 4
#define ROWE 512                       // [z][t] entries per column plane
#define PLANE_E (16 * ROWE)
#define PLANE_BYTES (PLANE_E * 8)      // 65536

#define CH_STRIDE (H*W*D*UP)           // 524288
#define OUT_CH (GH*GWD*GD)             // 2097152

__device__ __forceinline__ __half2 u2h(unsigned int u) {
    __half2 h; *reinterpret_cast<unsigned int*>(&h) = u; return h;
}
__device__ __forceinline__ unsigned int h2u(__half2 h) {
    return *reinterpret_cast<unsigned int*>(&h);
}

__global__ void __launch_bounds__(256, 3)
bgrid_slice_kernel(const float* __restrict__ bg,
                   const float* __restrict__ gm,
                   float* __restrict__ out)
{
    extern __shared__ uint2 S_plane[];           // [col][z][t] fp16x4
    __shared__ uint4 WX3[4];
    __shared__ uint4 WY3[4];

    const float sx = 31.0f / 127.0f;
    const int gh0 = blockIdx.y * TH;
    const int gw0 = blockIdx.x * TW;
    const int X = (int)floorf((float)gh0 * sx);
    const int Y = (int)floorf((float)gw0 * sx);
    const int tid = threadIdx.x;

    // ---- tiny weight tables (3-tap padded, branch-free downstream) ----
    if (tid < 8) {
        int l = tid & 3;
        int base = (tid < 4) ? gh0 : gw0;
        int O = (tid < 4) ? X : Y;
        float c = fminf((float)(base + l) * sx, 31.0f);
        float c0f = floorf(c);
        float f = c - c0f;
        int l0 = (int)c0f - O;                    // 0 or 1
        uint4 w3;
        if (l0 == 0) {
            w3.x = h2u(__float2half2_rn(1.f - f));
            w3.y = h2u(__float2half2_rn(f));
            w3.z = 0u;
        } else {
            w3.x = 0u;
            w3.y = h2u(__float2half2_rn(1.f - f));
            w3.z = h2u(__float2half2_rn(f));
        }
        w3.w = 0u;
        if (tid < 4) WX3[l] = w3; else WY3[l] = w3;
    }
    __syncthreads();

    // ---- phase 1: load 9 corner rows, blend in registers, STS planes ----
    int rowbase[9];
    #pragma unroll
    for (int r = 0; r < 9; r++) {
        int a = r / 3, b = r - a * 3;
        int gx = min(X + a, H - 1);
        int gy = min(Y + b, W - 1);
        rowbase[r] = (gx * W + gy) * ROWE;
    }

    #pragma unroll
    for (int k = 0; k < 2; k++) {
        const int zt = k * 256 + tid;

        uint2 R[9];
        #pragma unroll
        for (int r = 0; r < 9; r++) {
            int idx = rowbase[r] + zt;
            float f0 = bg[idx];
            float f1 = bg[idx + CH_STRIDE];
            float f2 = bg[idx + 2 * CH_STRIDE];
            float f3 = bg[idx + 3 * CH_STRIDE];
            R[r].x = h2u(__floats2half2_rn(f0, f1));
            R[r].y = h2u(__floats2half2_rn(f2, f3));
        }

        uint2 T[12];
        #pragma unroll
        for (int lw = 0; lw < 4; lw++) {
            uint4 wy = WY3[lw];
            __half2 w0 = u2h(wy.x), w1 = u2h(wy.y), w2 = u2h(wy.z);
            #pragma unroll
            for (int a = 0; a < 3; a++) {
                __half2 t01 = __hmul2(w0, u2h(R[a*3 + 0].x));
                t01 = __hfma2(w1, u2h(R[a*3 + 1].x), t01);
                t01 = __hfma2(w2, u2h(R[a*3 + 2].x), t01);
                __half2 t23 = __hmul2(w0, u2h(R[a*3 + 0].y));
                t23 = __hfma2(w1, u2h(R[a*3 + 1].y), t23);
                t23 = __hfma2(w2, u2h(R[a*3 + 2].y), t23);
                T[a*4 + lw].x = h2u(t01);
                T[a*4 + lw].y = h2u(t23);
            }
        }

        #pragma unroll
        for (int lh = 0; lh < 4; lh++) {
            uint4 wx = WX3[lh];
            __half2 w0 = u2h(wx.x), w1 = u2h(wx.y), w2 = u2h(wx.z);
            #pragma unroll
            for (int lw = 0; lw < 4; lw++) {
                __half2 o01 = __hmul2(w0, u2h(T[0*4 + lw].x));
                o01 = __hfma2(w1, u2h(T[1*4 + lw].x), o01);
                o01 = __hfma2(w2, u2h(T[2*4 + lw].x), o01);
                __half2 o23 = __hmul2(w0, u2h(T[0*4 + lw].y));
                o23 = __hfma2(w1, u2h(T[1*4 + lw].y), o23);
                o23 = __hfma2(w2, u2h(T[2*4 + lw].y), o23);
                uint2 o; o.x = h2u(o01); o.y = h2u(o23);
                S_plane[(lh*4 + lw) * ROWE + zt] = o;
            }
        }
    }
    __syncthreads();

    // ---- phase 2: gather with hoisted invariants ----
    // v = k*256 + tid  =>  gd = tid & 127 (k-invariant), c16 = 2k + (tid>>7)
    const int gd = tid & 127;
    const int hh = tid >> 7;

    // z-chain: fully loop-invariant
    float zc = fminf((float)gd * sx, 31.0f);
    float z0f = floorf(zc);
    float fz = zc - z0f;
    int z0 = (int)z0f;
    int z1 = min(z0 + 1, D - 1);
    const int z0o = z0 * 16;
    const int z1o = z1 * 16;
    const float wzA = 1.f - fz;

    // per-k column constants + batched gm prefetch (gm addr == out base addr)
    float g[8];
    int obase[8];
    int poff[8];
    #pragma unroll
    for (int k = 0; k < 8; k++) {
        int c16 = 2 * k + hh;
        int gh = gh0 + (c16 >> 2);
        int gw = gw0 + (c16 & 3);
        obase[k] = (gh * GWD + gw) * GD + gd;
        poff[k] = c16 * ROWE;
    }
    #pragma unroll
    for (int k = 0; k < 8; k++) g[k] = __ldg(&gm[obase[k]]);

    #pragma unroll
    for (int k = 0; k < 8; k++) {
        float t = fminf(fmaxf(g[k] * 15.0f, 0.0f), 15.0f);
        float t0f = floorf(t);
        float ft = t - t0f;
        int t0 = (int)t0f;
        int t1 = min(t0 + 1, UP - 1);

        const uint2* P = S_plane + poff[k];
        uint2 e00 = P[z0o + t0];
        uint2 e01 = P[z0o + t1];
        uint2 e10 = P[z1o + t0];
        uint2 e11 = P[z1o + t1];

        float w00 = wzA * (1.f - ft);
        float w01 = wzA * ft;
        float w10 = fz * (1.f - ft);
        float w11 = fz * ft;

        float2 a01 = __half22float2(u2h(e00.x));
        float2 a23 = __half22float2(u2h(e00.y));
        float acc0 = a01.x * w00, acc1 = a01.y * w00;
        float acc2 = a23.x * w00, acc3 = a23.y * w00;

        a01 = __half22float2(u2h(e01.x)); a23 = __half22float2(u2h(e01.y));
        acc0 = fmaf(a01.x, w01, acc0); acc1 = fmaf(a01.y, w01, acc1);
        acc2 = fmaf(a23.x, w01, acc2); acc3 = fmaf(a23.y, w01, acc3);

        a01 = __half22float2(u2h(e10.x)); a23 = __half22float2(u2h(e10.y));
        acc0 = fmaf(a01.x, w10, acc0); acc1 = fmaf(a01.y, w10, acc1);
        acc2 = fmaf(a23.x, w10, acc2); acc3 = fmaf(a23.y, w10, acc3);

        a01 = __half22float2(u2h(e11.x)); a23 = __half22float2(u2h(e11.y));
        acc0 = fmaf(a01.x, w11, acc0); acc1 = fmaf(a01.y, w11, acc1);
        acc2 = fmaf(a23.x, w11, acc2); acc3 = fmaf(a23.y, w11, acc3);

        int ob = obase[k];
        out[ob]              = acc0;
        out[ob + OUT_CH]     = acc1;
        out[ob + 2 * OUT_CH] = acc2;
        out[ob + 3 * OUT_CH] = acc3;
    }
}

extern "C" void kernel_launch(void* const* d_in, const int* in_sizes, int n_in,
                              void* d_out, int out_size)
{
    const float* bg = (const float*)d_in[0];
    const float* gm = (const float*)d_in[1];
    float* out = (float*)d_out;

    cudaFuncSetAttribute(bgrid_slice_kernel,
                         cudaFuncAttributeMaxDynamicSharedMemorySize, PLANE_BYTES);

    dim3 grid(GWD / TW, GH / TH);   // 32 x 32 = 1024 blocks
    bgrid_slice_kernel<<<grid, 256, PLANE_BYTES>>>(bg, gm, out);
}